// round 2
// baseline (speedup 1.0000x reference)
#include <cuda_runtime.h>
#include <cuda_bf16.h>
#include <math.h>

// Problem dims
#define BB   4
#define SS   2048
#define DD   512
#define HH   8
#define DKV  64
#define DFF  2048
#define MM   (BB * SS)     // 8192 rows

// ---------------------------------------------------------------------------
// Scratch (device globals — no allocation allowed)
// ---------------------------------------------------------------------------
__device__ float g_Q[MM * DD];
__device__ float g_K[MM * DD];
__device__ float g_V[MM * DD];
__device__ float g_T[MM * DD];    // attention output
__device__ float g_Y[MM * DD];    // residual 1 output
__device__ float g_F[MM * DFF];   // FFN hidden
__device__ unsigned char g_mask[BB * SS];
__device__ int g_mflag[1];

// ---------------------------------------------------------------------------
// Mask dtype detection: inspect first 8192 BYTES only (safe under any layout).
// flag: 0 = int32 storage, 1 = float32 storage, 2 = uint8 storage
// ---------------------------------------------------------------------------
__global__ void detect_mask_kernel(const void* __restrict__ m, int* __restrict__ flag)
{
    __shared__ int bad_int, bad_flt;
    if (threadIdx.x == 0) { bad_int = 0; bad_flt = 0; }
    __syncthreads();
    const int* mi = (const int*)m;
    const float* mf = (const float*)m;
    for (int i = threadIdx.x; i < 2048; i += 256) {
        int vi = mi[i];
        if (vi != 0 && vi != 1) bad_int = 1;
        float vf = mf[i];
        if (vf != 0.0f && vf != 1.0f) bad_flt = 1;
    }
    __syncthreads();
    if (threadIdx.x == 0) flag[0] = bad_int ? (bad_flt ? 2 : 1) : 0;
}

__global__ void expand_mask_kernel(const void* __restrict__ m, const int* __restrict__ flag,
                                   unsigned char* __restrict__ out)
{
    int i = blockIdx.x * 256 + threadIdx.x;
    if (i >= BB * SS) return;
    int f = flag[0];
    unsigned char v;
    if (f == 0)      v = (((const int*)m)[i]   != 0)    ? 1 : 0;
    else if (f == 1) v = (((const float*)m)[i] != 0.0f) ? 1 : 0;
    else             v = (((const unsigned char*)m)[i] != 0) ? 1 : 0;
    out[i] = v;
}

// ---------------------------------------------------------------------------
// Generic GEMM: C[M,N] = A[M,K] @ W[N,K]^T + bias[N], optional ReLU
// 128x128 block tile, K-tile 8, 256 threads, 8x8 per-thread register blocking
// ---------------------------------------------------------------------------
__global__ __launch_bounds__(256, 2)
void gemm_kernel(const float* __restrict__ A, const float* __restrict__ W,
                 const float* __restrict__ bias, float* __restrict__ C,
                 int M, int N, int K, int relu)
{
    __shared__ float As[8][128];
    __shared__ float Ws[8][128];

    const int tid = threadIdx.x;
    const int tr  = tid >> 4;           // 0..15  (row group, *8)
    const int tc  = tid & 15;           // 0..15  (col group, *8)
    const int bm  = blockIdx.y * 128;
    const int bn  = blockIdx.x * 128;

    const int lr = tid >> 1;            // 0..127
    const int lk = (tid & 1) * 4;       // 0 or 4

    const float* Ag = A + (size_t)(bm + lr) * K + lk;
    const float* Wg = W + (size_t)(bn + lr) * K + lk;

    float acc[8][8];
#pragma unroll
    for (int i = 0; i < 8; i++)
#pragma unroll
        for (int j = 0; j < 8; j++) acc[i][j] = 0.f;

    for (int k0 = 0; k0 < K; k0 += 8) {
        float4 av = *(const float4*)(Ag + k0);
        float4 wv = *(const float4*)(Wg + k0);
        __syncthreads();
        As[lk + 0][lr] = av.x; As[lk + 1][lr] = av.y;
        As[lk + 2][lr] = av.z; As[lk + 3][lr] = av.w;
        Ws[lk + 0][lr] = wv.x; Ws[lk + 1][lr] = wv.y;
        Ws[lk + 2][lr] = wv.z; Ws[lk + 3][lr] = wv.w;
        __syncthreads();

#pragma unroll
        for (int kk = 0; kk < 8; kk++) {
            float a[8], b[8];
            *(float4*)(a)     = *(const float4*)&As[kk][tr * 8];
            *(float4*)(a + 4) = *(const float4*)&As[kk][tr * 8 + 4];
            *(float4*)(b)     = *(const float4*)&Ws[kk][tc * 8];
            *(float4*)(b + 4) = *(const float4*)&Ws[kk][tc * 8 + 4];
#pragma unroll
            for (int i = 0; i < 8; i++)
#pragma unroll
                for (int j = 0; j < 8; j++)
                    acc[i][j] = fmaf(a[i], b[j], acc[i][j]);
        }
    }

    float bv[8];
    *(float4*)(bv)     = *(const float4*)(bias + bn + tc * 8);
    *(float4*)(bv + 4) = *(const float4*)(bias + bn + tc * 8 + 4);

#pragma unroll
    for (int i = 0; i < 8; i++) {
        float o[8];
#pragma unroll
        for (int j = 0; j < 8; j++) {
            float v = acc[i][j] + bv[j];
            o[j] = relu ? fmaxf(v, 0.f) : v;
        }
        float* Cr = C + (size_t)(bm + tr * 8 + i) * N + bn + tc * 8;
        *(float4*)(Cr)     = *(const float4*)(o);
        *(float4*)(Cr + 4) = *(const float4*)(o + 4);
    }
}

// ---------------------------------------------------------------------------
// Flash-style attention. One block per (b, h, 64-query tile). 128 threads.
// ---------------------------------------------------------------------------
__global__ __launch_bounds__(128)
void attention_kernel(const float* __restrict__ Q, const float* __restrict__ K,
                      const float* __restrict__ V, const unsigned char* __restrict__ mask,
                      float* __restrict__ O)
{
    __shared__ float Qs[64 * 64];   // Q^T  : Qs[d*64 + r]
    __shared__ float Ab[64 * 64];   // K^T  : Ab[d*64 + c]  then  P^T : Ab[k*64 + r]
    __shared__ float Vs[64 * 64];   // V    : Vs[k*64 + d]

    const int b  = blockIdx.z;
    const int h  = blockIdx.y;
    const int q0 = blockIdx.x * 64;
    const int tid = threadIdx.x;
    const int ty = tid >> 3;            // 0..15
    const int tx = tid & 7;             // 0..7
    const int r0 = ty * 4;
    const int c0 = tx * 8;

    // load Q tile (transposed)
    {
        const float* Qg = Q + ((size_t)b * SS + q0) * DD + h * DKV;
#pragma unroll
        for (int pass = 0; pass < 8; pass++) {
            int rr = (tid >> 4) + pass * 8;
            int cc = (tid & 15) * 4;
            float4 v = *(const float4*)(Qg + (size_t)rr * DD + cc);
            Qs[(cc + 0) * 64 + rr] = v.x;
            Qs[(cc + 1) * 64 + rr] = v.y;
            Qs[(cc + 2) * 64 + rr] = v.z;
            Qs[(cc + 3) * 64 + rr] = v.w;
        }
    }

    float m[4], l[4], acc[4][8];
#pragma unroll
    for (int i = 0; i < 4; i++) {
        m[i] = -1e30f; l[i] = 0.f;
#pragma unroll
        for (int j = 0; j < 8; j++) acc[i][j] = 0.f;
    }

    const unsigned char* mk = mask + (size_t)b * SS;

    for (int j0 = 0; j0 < SS; j0 += 64) {
        const float* Kg = K + ((size_t)b * SS + j0) * DD + h * DKV;
        const float* Vg = V + ((size_t)b * SS + j0) * DD + h * DKV;

        __syncthreads();   // previous iteration done with Ab (P) & Vs
#pragma unroll
        for (int pass = 0; pass < 8; pass++) {
            int rr = (tid >> 4) + pass * 8;
            int cc = (tid & 15) * 4;
            float4 kv = *(const float4*)(Kg + (size_t)rr * DD + cc);
            Ab[(cc + 0) * 64 + rr] = kv.x;
            Ab[(cc + 1) * 64 + rr] = kv.y;
            Ab[(cc + 2) * 64 + rr] = kv.z;
            Ab[(cc + 3) * 64 + rr] = kv.w;
            float4 vv = *(const float4*)(Vg + (size_t)rr * DD + cc);
            *(float4*)(Vs + rr * 64 + cc) = vv;
        }
        __syncthreads();

        // S = Q K^T for this tile
        float s[4][8];
#pragma unroll
        for (int i = 0; i < 4; i++)
#pragma unroll
            for (int j = 0; j < 8; j++) s[i][j] = 0.f;

#pragma unroll
        for (int d = 0; d < 64; d++) {
            float a[4], bfr[8];
            *(float4*)(a)       = *(const float4*)&Qs[d * 64 + r0];
            *(float4*)(bfr)     = *(const float4*)&Ab[d * 64 + c0];
            *(float4*)(bfr + 4) = *(const float4*)&Ab[d * 64 + c0 + 4];
#pragma unroll
            for (int i = 0; i < 4; i++)
#pragma unroll
                for (int j = 0; j < 8; j++)
                    s[i][j] = fmaf(a[i], bfr[j], s[i][j]);
        }
        __syncthreads();   // everyone done reading Ab(K); safe to overwrite with P

        // mask + scale (masked value is exactly -1e9, NOT scaled — matches ref)
        unsigned char mv[8];
#pragma unroll
        for (int j = 0; j < 8; j++) mv[j] = mk[j0 + c0 + j];
#pragma unroll
        for (int i = 0; i < 4; i++)
#pragma unroll
            for (int j = 0; j < 8; j++)
                s[i][j] = mv[j] ? -1.0e9f : s[i][j] * 0.125f;

        // online softmax update
#pragma unroll
        for (int i = 0; i < 4; i++) {
            float tmax = s[i][0];
#pragma unroll
            for (int j = 1; j < 8; j++) tmax = fmaxf(tmax, s[i][j]);
#pragma unroll
            for (int off = 1; off < 8; off <<= 1)
                tmax = fmaxf(tmax, __shfl_xor_sync(0xffffffffu, tmax, off));

            float mn = fmaxf(m[i], tmax);
            float alpha = __expf(m[i] - mn);
            float rsum = 0.f;
#pragma unroll
            for (int j = 0; j < 8; j++) {
                s[i][j] = __expf(s[i][j] - mn);
                rsum += s[i][j];
            }
#pragma unroll
            for (int off = 1; off < 8; off <<= 1)
                rsum += __shfl_xor_sync(0xffffffffu, rsum, off);

            l[i] = l[i] * alpha + rsum;
            m[i] = mn;
#pragma unroll
            for (int j = 0; j < 8; j++) acc[i][j] *= alpha;
        }

        // write P^T into Ab: Ab[k*64 + r]
#pragma unroll
        for (int i = 0; i < 4; i++)
#pragma unroll
            for (int j = 0; j < 8; j++)
                Ab[(c0 + j) * 64 + (r0 + i)] = s[i][j];
        __syncthreads();

        // O += P V
#pragma unroll
        for (int k = 0; k < 64; k++) {
            float p[4], v[8];
            *(float4*)(p)     = *(const float4*)&Ab[k * 64 + r0];
            *(float4*)(v)     = *(const float4*)&Vs[k * 64 + c0];
            *(float4*)(v + 4) = *(const float4*)&Vs[k * 64 + c0 + 4];
#pragma unroll
            for (int i = 0; i < 4; i++)
#pragma unroll
                for (int j = 0; j < 8; j++)
                    acc[i][j] = fmaf(p[i], v[j], acc[i][j]);
        }
    }

    // epilogue
    float* Og = O + ((size_t)b * SS + q0) * DD + h * DKV;
#pragma unroll
    for (int i = 0; i < 4; i++) {
        float inv = 1.0f / l[i];
        float o[8];
#pragma unroll
        for (int j = 0; j < 8; j++) o[j] = acc[i][j] * inv;
        float* row = Og + (size_t)(r0 + i) * DD + c0;
        *(float4*)(row)     = *(const float4*)(o);
        *(float4*)(row + 4) = *(const float4*)(o + 4);
    }
}

// ---------------------------------------------------------------------------
// Residual + LayerNorm (unbiased var, scalar gamma/beta):
//   out = X + g * (Z - mean) / sqrt(var + eps) + beta
// ---------------------------------------------------------------------------
__global__ __launch_bounds__(128)
void ln_add_kernel(const float* __restrict__ X, const float* __restrict__ Z,
                   const float* __restrict__ g, const float* __restrict__ beta,
                   float* __restrict__ Out)
{
    __shared__ float red[4];
    const int row = blockIdx.x;
    const int t = threadIdx.x;
    const float4 zv = ((const float4*)(Z + (size_t)row * DD))[t];

    // sum
    float s = zv.x + zv.y + zv.z + zv.w;
#pragma unroll
    for (int off = 16; off > 0; off >>= 1) s += __shfl_down_sync(0xffffffffu, s, off);
    if ((t & 31) == 0) red[t >> 5] = s;
    __syncthreads();
    float mean = (red[0] + red[1] + red[2] + red[3]) * (1.0f / DD);
    __syncthreads();

    float d0 = zv.x - mean, d1 = zv.y - mean, d2 = zv.z - mean, d3 = zv.w - mean;
    float ss = d0 * d0 + d1 * d1 + d2 * d2 + d3 * d3;
#pragma unroll
    for (int off = 16; off > 0; off >>= 1) ss += __shfl_down_sync(0xffffffffu, ss, off);
    if ((t & 31) == 0) red[t >> 5] = ss;
    __syncthreads();
    float var = (red[0] + red[1] + red[2] + red[3]) * (1.0f / (DD - 1));

    float inv = rsqrtf(var + 1e-6f);
    float gg = *g, bb = *beta;

    const float4 xv = ((const float4*)(X + (size_t)row * DD))[t];
    float4 o;
    o.x = xv.x + gg * d0 * inv + bb;
    o.y = xv.y + gg * d1 * inv + bb;
    o.z = xv.z + gg * d2 * inv + bb;
    o.w = xv.w + gg * d3 * inv + bb;
    ((float4*)(Out + (size_t)row * DD))[t] = o;
}

// ---------------------------------------------------------------------------
// Launch
// ---------------------------------------------------------------------------
extern "C" void kernel_launch(void* const* d_in, const int* in_sizes, int n_in,
                              void* d_out, int out_size)
{
    const float* x    = (const float*)d_in[0];
    const void*  mraw = (const void*)d_in[1];
    const float* wq   = (const float*)d_in[2];
    const float* bq   = (const float*)d_in[3];
    const float* wk   = (const float*)d_in[4];
    const float* bk   = (const float*)d_in[5];
    const float* wv   = (const float*)d_in[6];
    const float* bv   = (const float*)d_in[7];
    const float* wo   = (const float*)d_in[8];
    const float* bo   = (const float*)d_in[9];
    const float* w1   = (const float*)d_in[10];
    const float* b1   = (const float*)d_in[11];
    const float* w2   = (const float*)d_in[12];
    const float* b2   = (const float*)d_in[13];
    const float* g1   = (const float*)d_in[14];
    const float* be1  = (const float*)d_in[15];
    const float* g2   = (const float*)d_in[16];
    const float* be2  = (const float*)d_in[17];
    float* out = (float*)d_out;

    float *pQ, *pK, *pV, *pT, *pY, *pF;
    unsigned char* pM; int* pMF;
    cudaGetSymbolAddress((void**)&pQ, g_Q);
    cudaGetSymbolAddress((void**)&pK, g_K);
    cudaGetSymbolAddress((void**)&pV, g_V);
    cudaGetSymbolAddress((void**)&pT, g_T);
    cudaGetSymbolAddress((void**)&pY, g_Y);
    cudaGetSymbolAddress((void**)&pF, g_F);
    cudaGetSymbolAddress((void**)&pM, g_mask);
    cudaGetSymbolAddress((void**)&pMF, g_mflag);

    // canonicalize mask
    detect_mask_kernel<<<1, 256>>>(mraw, pMF);
    expand_mask_kernel<<<(BB * SS + 255) / 256, 256>>>(mraw, pMF, pM);

    dim3 gProj(DD / 128, MM / 128);       // (4, 64)
    dim3 gFF1(DFF / 128, MM / 128);       // (16, 64)

    // Q, K, V projections
    gemm_kernel<<<gProj, 256>>>(x, wq, bq, pQ, MM, DD, DD, 0);
    gemm_kernel<<<gProj, 256>>>(x, wk, bk, pK, MM, DD, DD, 0);
    gemm_kernel<<<gProj, 256>>>(x, wv, bv, pV, MM, DD, DD, 0);

    // attention
    dim3 gAtt(SS / 64, HH, BB);           // (32, 8, 4)
    attention_kernel<<<gAtt, 128>>>(pQ, pK, pV, pM, pT);

    // output projection (into g_Q, which is free now)
    gemm_kernel<<<gProj, 256>>>(pT, wo, bo, pQ, MM, DD, DD, 0);

    // residual 1 + layernorm
    ln_add_kernel<<<MM, 128>>>(x, pQ, g1, be1, pY);

    // FFN
    gemm_kernel<<<gFF1, 256>>>(pY, w1, b1, pF, MM, DFF, DD, 1);
    gemm_kernel<<<gProj, 256>>>(pF, w2, b2, pK, MM, DD, DFF, 0);

    // residual 2 + layernorm -> output
    ln_add_kernel<<<MM, 128>>>(pY, pK, g2, be2, out);
}

// round 4
// speedup vs baseline: 1.4105x; 1.4105x over previous
#include <cuda_runtime.h>
#include <cuda_bf16.h>
#include <math.h>
#include <stdint.h>

// Problem dims
#define BB   4
#define SS   2048
#define DD   512
#define HH   8
#define DKV  64
#define DFF  2048
#define MM   (BB * SS)     // 8192 rows
#define QKVN 1536          // fused Q|K|V output width

// ---------------------------------------------------------------------------
// Scratch (device globals — no allocation allowed)
// ---------------------------------------------------------------------------
__device__ __align__(256) float g_QKV[MM * QKVN];   // fused QKV projection out
__device__ __align__(256) float g_O[MM * DD];       // gemm fp32 out (WO / FFN2)
__device__ __align__(256) float g_Y[MM * DD];       // residual-1 output
__device__ __align__(256) __nv_bfloat16 g_Ahi[MM * DD];   // activation splits [M,512]
__device__ __align__(256) __nv_bfloat16 g_Alo[MM * DD];
__device__ __align__(256) __nv_bfloat16 g_Fhi[MM * DFF];  // FFN hidden splits
__device__ __align__(256) __nv_bfloat16 g_Flo[MM * DFF];
// weights [N,K] row-major, concatenated: qkv rows 0..1535 (K=512), wo, w1, w2
#define WOFF_QKV 0
#define WOFF_O   (QKVN * DD)                  // 786432
#define WOFF_1   (WOFF_O + DD * DD)           // 1048576
#define WOFF_2   (WOFF_1 + DFF * DD)          // 2097152
#define WTOT     (WOFF_2 + DD * DFF)          // 3145728
__device__ __align__(256) __nv_bfloat16 g_Whi[WTOT];
__device__ __align__(256) __nv_bfloat16 g_Wlo[WTOT];
__device__ float g_biasQKV[QKVN];
__device__ unsigned char g_mask[BB * SS];
__device__ int g_mflag[1];

// ---------------------------------------------------------------------------
// Helpers
// ---------------------------------------------------------------------------
__device__ __forceinline__ uint32_t smem_u32(const void* p) {
    uint32_t a;
    asm("{ .reg .u64 t; cvta.to.shared.u64 t, %1; cvt.u32.u64 %0, t; }" : "=r"(a) : "l"(p));
    return a;
}
__device__ __forceinline__ void cp16(uint32_t d, const void* g) {
    asm volatile("cp.async.cg.shared.global [%0], [%1], 16;" :: "r"(d), "l"(g));
}
#define CP_COMMIT() asm volatile("cp.async.commit_group;" ::: "memory")
#define CP_WAIT0()  asm volatile("cp.async.wait_group 0;" ::: "memory")
#define CP_WAIT1()  asm volatile("cp.async.wait_group 1;" ::: "memory")

#define LDSM4(r0, r1, r2, r3, a) \
    asm volatile("ldmatrix.sync.aligned.m8n8.x4.shared.b16 {%0,%1,%2,%3}, [%4];" \
                 : "=r"(r0), "=r"(r1), "=r"(r2), "=r"(r3) : "r"(a))

#define MMA16816(d, a, b) \
    asm volatile("mma.sync.aligned.m16n8k16.row.col.f32.bf16.bf16.f32 " \
                 "{%0,%1,%2,%3},{%4,%5,%6,%7},{%8,%9},{%0,%1,%2,%3};" \
                 : "+f"((d)[0]), "+f"((d)[1]), "+f"((d)[2]), "+f"((d)[3]) \
                 : "r"((a)[0]), "r"((a)[1]), "r"((a)[2]), "r"((a)[3]), \
                   "r"((b)[0]), "r"((b)[1]))

// ---------------------------------------------------------------------------
// Mask canonicalization
// ---------------------------------------------------------------------------
__global__ void detect_mask_kernel(const void* __restrict__ m, int* __restrict__ flag)
{
    __shared__ int bad_int, bad_flt;
    if (threadIdx.x == 0) { bad_int = 0; bad_flt = 0; }
    __syncthreads();
    const int* mi = (const int*)m;
    const float* mf = (const float*)m;
    for (int i = threadIdx.x; i < 2048; i += 256) {
        int vi = mi[i];
        if (vi != 0 && vi != 1) bad_int = 1;
        float vf = mf[i];
        if (vf != 0.0f && vf != 1.0f) bad_flt = 1;
    }
    __syncthreads();
    if (threadIdx.x == 0) flag[0] = bad_int ? (bad_flt ? 2 : 1) : 0;
}

__global__ void expand_mask_kernel(const void* __restrict__ m, const int* __restrict__ flag,
                                   unsigned char* __restrict__ out)
{
    int i = blockIdx.x * 256 + threadIdx.x;
    if (i >= BB * SS) return;
    int f = flag[0];
    unsigned char v;
    if (f == 0)      v = (((const int*)m)[i]   != 0)    ? 1 : 0;
    else if (f == 1) v = (((const float*)m)[i] != 0.0f) ? 1 : 0;
    else             v = (((const unsigned char*)m)[i] != 0) ? 1 : 0;
    out[i] = v;
}

__global__ void concat_bias_kernel(const float* __restrict__ a, const float* __restrict__ b,
                                   const float* __restrict__ c, float* __restrict__ o)
{
    int i = blockIdx.x * 256 + threadIdx.x;
    if (i < 512)          o[i] = a[i];
    else if (i < 1024)    o[i] = b[i - 512];
    else if (i < QKVN)    o[i] = c[i - 1024];
}

// ---------------------------------------------------------------------------
// fp32 -> bf16 hi/lo split
// ---------------------------------------------------------------------------
__global__ __launch_bounds__(256)
void split_bf16_kernel(const float* __restrict__ in, __nv_bfloat16* __restrict__ hi,
                       __nv_bfloat16* __restrict__ lo, int n)
{
    int i = (blockIdx.x * 256 + threadIdx.x) * 4;
    if (i >= n) return;
    float4 v = *(const float4*)(in + i);
    __nv_bfloat16 h0 = __float2bfloat16_rn(v.x);
    __nv_bfloat16 h1 = __float2bfloat16_rn(v.y);
    __nv_bfloat16 h2 = __float2bfloat16_rn(v.z);
    __nv_bfloat16 h3 = __float2bfloat16_rn(v.w);
    __nv_bfloat16 l0 = __float2bfloat16_rn(v.x - __bfloat162float(h0));
    __nv_bfloat16 l1 = __float2bfloat16_rn(v.y - __bfloat162float(h1));
    __nv_bfloat16 l2 = __float2bfloat16_rn(v.z - __bfloat162float(h2));
    __nv_bfloat16 l3 = __float2bfloat16_rn(v.w - __bfloat162float(h3));
    __nv_bfloat162 hv0; hv0.x = h0; hv0.y = h1;
    __nv_bfloat162 hv1; hv1.x = h2; hv1.y = h3;
    __nv_bfloat162 lv0; lv0.x = l0; lv0.y = l1;
    __nv_bfloat162 lv1; lv1.x = l2; lv1.y = l3;
    *(uint2*)(hi + i) = make_uint2(*(uint32_t*)&hv0, *(uint32_t*)&hv1);
    *(uint2*)(lo + i) = make_uint2(*(uint32_t*)&lv0, *(uint32_t*)&lv1);
}

// ---------------------------------------------------------------------------
// mma.sync bf16 split-GEMM:
//   C[M,N] = (Ahi+Alo)[M,K] @ (Whi+Wlo)[N,K]^T + bias  (3 passes: hh, lh, hl)
// CTA tile 128x128, 8 warps (2m x 4n -> warp 64x32), BK=32, 2-stage cp.async.
// smem per stage: Ahi,Alo,Bhi,Blo each 128 rows x 40 bf16 (80B pitch).
// Outputs: optional fp32 Cf, optional bf16 split (Chi, Clo). relu applies first.
// ---------------------------------------------------------------------------
#define TPAD 40
#define TILE_B (128 * TPAD * 2)     // 10240
#define STAGE_B (4 * TILE_B)        // 40960
#define GSMEM (2 * STAGE_B)         // 81920

__device__ __forceinline__ void gemm_issue(uint32_t sb, int stage, const __nv_bfloat16* const* srcs,
                                           int K, int kt, int tid)
{
    uint32_t stbase = sb + stage * STAGE_B;
    const int k0 = kt * 32;
#pragma unroll
    for (int t = 0; t < 4; t++) {
        const __nv_bfloat16* s = srcs[t] + k0;
#pragma unroll
        for (int i = 0; i < 2; i++) {
            int idx = tid + i * 256;
            int row = idx >> 2, ch = idx & 3;
            cp16(stbase + t * TILE_B + row * (TPAD * 2) + ch * 16,
                 s + (size_t)row * K + ch * 8);
        }
    }
    CP_COMMIT();
}

__global__ __launch_bounds__(256, 1)
void gemm_mma(const __nv_bfloat16* __restrict__ Ahi, const __nv_bfloat16* __restrict__ Alo,
              const __nv_bfloat16* __restrict__ Whi, const __nv_bfloat16* __restrict__ Wlo,
              const float* __restrict__ bias, float* __restrict__ Cf,
              __nv_bfloat16* __restrict__ Chi, __nv_bfloat16* __restrict__ Clo,
              int M, int N, int K, int relu)
{
    extern __shared__ char sm[];
    const uint32_t sb = smem_u32(sm);
    const int tid = threadIdx.x;
    const int wid = tid >> 5;
    const int lane = tid & 31;
    const int bm = blockIdx.y * 128;
    const int bn = blockIdx.x * 128;
    const int wm = (wid & 1) * 64;
    const int wn = (wid >> 1) * 32;

    const __nv_bfloat16* srcs[4];
    srcs[0] = Ahi + (size_t)bm * K;
    srcs[1] = Alo + (size_t)bm * K;
    srcs[2] = Whi + (size_t)bn * K;
    srcs[3] = Wlo + (size_t)bn * K;

    float acc[4][4][4];
#pragma unroll
    for (int i = 0; i < 4; i++)
#pragma unroll
        for (int j = 0; j < 4; j++)
#pragma unroll
            for (int r = 0; r < 4; r++) acc[i][j][r] = 0.f;

    const int KT = K >> 5;
    gemm_issue(sb, 0, srcs, K, 0, tid);
    gemm_issue(sb, 1, srcs, K, 1, tid);

    // lane-dependent ldmatrix offsets (bytes within a tile)
    const int a_lofs = ((((lane >> 3) & 1) << 3) + (lane & 7)) * (TPAD * 2) + ((lane >> 4) << 4);
    const int b_lofs = ((((lane >> 4) & 1) << 3) + (lane & 7)) * (TPAD * 2) + (((lane >> 3) & 1) << 4);

    for (int kt = 0; kt < KT; kt++) {
        if (kt == KT - 1) { CP_WAIT0(); } else { CP_WAIT1(); }
        __syncthreads();
        const uint32_t base = sb + (kt & 1) * STAGE_B;

#pragma unroll
        for (int ks = 0; ks < 2; ks++) {
            uint32_t ah[4][4], al[4][4], bh[4][2], bl[4][2];
            const uint32_t aoff = base + (wm)*(TPAD * 2) + ks * 32 + a_lofs;
            const uint32_t boff = base + 2 * TILE_B + (wn)*(TPAD * 2) + ks * 32 + b_lofs;
#pragma unroll
            for (int i = 0; i < 4; i++) {
                LDSM4(ah[i][0], ah[i][1], ah[i][2], ah[i][3], aoff + i * 16 * (TPAD * 2));
                LDSM4(al[i][0], al[i][1], al[i][2], al[i][3], aoff + TILE_B + i * 16 * (TPAD * 2));
            }
#pragma unroll
            for (int g = 0; g < 2; g++) {
                LDSM4(bh[2 * g][0], bh[2 * g][1], bh[2 * g + 1][0], bh[2 * g + 1][1],
                      boff + g * 16 * (TPAD * 2));
                LDSM4(bl[2 * g][0], bl[2 * g][1], bl[2 * g + 1][0], bl[2 * g + 1][1],
                      boff + TILE_B + g * 16 * (TPAD * 2));
            }
#pragma unroll
            for (int i = 0; i < 4; i++)
#pragma unroll
                for (int j = 0; j < 4; j++) MMA16816(acc[i][j], ah[i], bh[j]);
#pragma unroll
            for (int i = 0; i < 4; i++)
#pragma unroll
                for (int j = 0; j < 4; j++) MMA16816(acc[i][j], al[i], bh[j]);
#pragma unroll
            for (int i = 0; i < 4; i++)
#pragma unroll
                for (int j = 0; j < 4; j++) MMA16816(acc[i][j], ah[i], bl[j]);
        }
        __syncthreads();
        if (kt + 2 < KT) gemm_issue(sb, kt & 1, srcs, K, kt + 2, tid);
    }

    // epilogue
    const int rr = lane >> 2;
    const int cc = (lane & 3) * 2;
#pragma unroll
    for (int i = 0; i < 4; i++) {
#pragma unroll
        for (int j = 0; j < 4; j++) {
            int r0 = bm + wm + i * 16 + rr;
            int c = bn + wn + j * 8 + cc;
            float b0 = __ldg(bias + c), b1 = __ldg(bias + c + 1);
            float v00 = acc[i][j][0] + b0, v01 = acc[i][j][1] + b1;
            float v10 = acc[i][j][2] + b0, v11 = acc[i][j][3] + b1;
            if (relu) {
                v00 = fmaxf(v00, 0.f); v01 = fmaxf(v01, 0.f);
                v10 = fmaxf(v10, 0.f); v11 = fmaxf(v11, 0.f);
            }
            size_t o0 = (size_t)r0 * N + c;
            size_t o1 = (size_t)(r0 + 8) * N + c;
            if (Cf) {
                *(float2*)(Cf + o0) = make_float2(v00, v01);
                *(float2*)(Cf + o1) = make_float2(v10, v11);
            }
            if (Chi) {
                __nv_bfloat162 h0 = __floats2bfloat162_rn(v00, v01);
                __nv_bfloat162 h1 = __floats2bfloat162_rn(v10, v11);
                __nv_bfloat162 l0 = __floats2bfloat162_rn(v00 - __bfloat162float(h0.x),
                                                          v01 - __bfloat162float(h0.y));
                __nv_bfloat162 l1 = __floats2bfloat162_rn(v10 - __bfloat162float(h1.x),
                                                          v11 - __bfloat162float(h1.y));
                *(__nv_bfloat162*)(Chi + o0) = h0;
                *(__nv_bfloat162*)(Chi + o1) = h1;
                *(__nv_bfloat162*)(Clo + o0) = l0;
                *(__nv_bfloat162*)(Clo + o1) = l1;
            }
        }
    }
}

// ---------------------------------------------------------------------------
// Flash-style attention (fp32 SIMT). Reads fused QKV [M,1536].
// Writes attention output directly as bf16 hi/lo splits [M,512].
// ---------------------------------------------------------------------------
#define QP 1536

__global__ __launch_bounds__(128)
void attention_kernel(const float* __restrict__ QKV, const unsigned char* __restrict__ mask,
                      __nv_bfloat16* __restrict__ Ohi, __nv_bfloat16* __restrict__ Olo)
{
    __shared__ float Qs[64 * 64];
    __shared__ float Ab[64 * 64];
    __shared__ float Vs[64 * 64];

    const int b  = blockIdx.z;
    const int h  = blockIdx.y;
    const int q0 = blockIdx.x * 64;
    const int tid = threadIdx.x;
    const int ty = tid >> 3;
    const int tx = tid & 7;
    const int r0 = ty * 4;
    const int c0 = tx * 8;

    {
        const float* Qg = QKV + ((size_t)b * SS + q0) * QP + h * DKV;
#pragma unroll
        for (int pass = 0; pass < 8; pass++) {
            int rr = (tid >> 4) + pass * 8;
            int cc = (tid & 15) * 4;
            float4 v = *(const float4*)(Qg + (size_t)rr * QP + cc);
            Qs[(cc + 0) * 64 + rr] = v.x;
            Qs[(cc + 1) * 64 + rr] = v.y;
            Qs[(cc + 2) * 64 + rr] = v.z;
            Qs[(cc + 3) * 64 + rr] = v.w;
        }
    }

    float m[4], l[4], acc[4][8];
#pragma unroll
    for (int i = 0; i < 4; i++) {
        m[i] = -1e30f; l[i] = 0.f;
#pragma unroll
        for (int j = 0; j < 8; j++) acc[i][j] = 0.f;
    }

    const unsigned char* mk = mask + (size_t)b * SS;

    for (int j0 = 0; j0 < SS; j0 += 64) {
        const float* Kg = QKV + ((size_t)b * SS + j0) * QP + 512 + h * DKV;
        const float* Vg = QKV + ((size_t)b * SS + j0) * QP + 1024 + h * DKV;

        __syncthreads();
#pragma unroll
        for (int pass = 0; pass < 8; pass++) {
            int rr = (tid >> 4) + pass * 8;
            int cc = (tid & 15) * 4;
            float4 kv = *(const float4*)(Kg + (size_t)rr * QP + cc);
            Ab[(cc + 0) * 64 + rr] = kv.x;
            Ab[(cc + 1) * 64 + rr] = kv.y;
            Ab[(cc + 2) * 64 + rr] = kv.z;
            Ab[(cc + 3) * 64 + rr] = kv.w;
            float4 vv = *(const float4*)(Vg + (size_t)rr * QP + cc);
            *(float4*)(Vs + rr * 64 + cc) = vv;
        }
        __syncthreads();

        float s[4][8];
#pragma unroll
        for (int i = 0; i < 4; i++)
#pragma unroll
            for (int j = 0; j < 8; j++) s[i][j] = 0.f;

#pragma unroll
        for (int d = 0; d < 64; d++) {
            float a[4], bfr[8];
            *(float4*)(a)       = *(const float4*)&Qs[d * 64 + r0];
            *(float4*)(bfr)     = *(const float4*)&Ab[d * 64 + c0];
            *(float4*)(bfr + 4) = *(const float4*)&Ab[d * 64 + c0 + 4];
#pragma unroll
            for (int i = 0; i < 4; i++)
#pragma unroll
                for (int j = 0; j < 8; j++)
                    s[i][j] = fmaf(a[i], bfr[j], s[i][j]);
        }
        __syncthreads();

        unsigned char mv[8];
#pragma unroll
        for (int j = 0; j < 8; j++) mv[j] = mk[j0 + c0 + j];
#pragma unroll
        for (int i = 0; i < 4; i++)
#pragma unroll
            for (int j = 0; j < 8; j++)
                s[i][j] = mv[j] ? -1.0e9f : s[i][j] * 0.125f;

#pragma unroll
        for (int i = 0; i < 4; i++) {
            float tmax = s[i][0];
#pragma unroll
            for (int j = 1; j < 8; j++) tmax = fmaxf(tmax, s[i][j]);
#pragma unroll
            for (int off = 1; off < 8; off <<= 1)
                tmax = fmaxf(tmax, __shfl_xor_sync(0xffffffffu, tmax, off));

            float mn = fmaxf(m[i], tmax);
            float alpha = __expf(m[i] - mn);
            float rsum = 0.f;
#pragma unroll
            for (int j = 0; j < 8; j++) {
                s[i][j] = __expf(s[i][j] - mn);
                rsum += s[i][j];
            }
#pragma unroll
            for (int off = 1; off < 8; off <<= 1)
                rsum += __shfl_xor_sync(0xffffffffu, rsum, off);

            l[i] = l[i] * alpha + rsum;
            m[i] = mn;
#pragma unroll
            for (int j = 0; j < 8; j++) acc[i][j] *= alpha;
        }

#pragma unroll
        for (int i = 0; i < 4; i++)
#pragma unroll
            for (int j = 0; j < 8; j++)
                Ab[(c0 + j) * 64 + (r0 + i)] = s[i][j];
        __syncthreads();

#pragma unroll
        for (int k = 0; k < 64; k++) {
            float p[4], v[8];
            *(float4*)(p)     = *(const float4*)&Ab[k * 64 + r0];
            *(float4*)(v)     = *(const float4*)&Vs[k * 64 + c0];
            *(float4*)(v + 4) = *(const float4*)&Vs[k * 64 + c0 + 4];
#pragma unroll
            for (int i = 0; i < 4; i++)
#pragma unroll
                for (int j = 0; j < 8; j++)
                    acc[i][j] = fmaf(p[i], v[j], acc[i][j]);
        }
    }

    // epilogue: write bf16 hi/lo split of O
#pragma unroll
    for (int i = 0; i < 4; i++) {
        float inv = 1.0f / l[i];
        size_t off = ((size_t)b * SS + q0 + r0 + i) * DD + h * DKV + c0;
#pragma unroll
        for (int j = 0; j < 8; j += 2) {
            float v0 = acc[i][j] * inv, v1 = acc[i][j + 1] * inv;
            __nv_bfloat162 hv = __floats2bfloat162_rn(v0, v1);
            __nv_bfloat162 lv = __floats2bfloat162_rn(v0 - __bfloat162float(hv.x),
                                                      v1 - __bfloat162float(hv.y));
            *(__nv_bfloat162*)(Ohi + off + j) = hv;
            *(__nv_bfloat162*)(Olo + off + j) = lv;
        }
    }
}

// ---------------------------------------------------------------------------
// Residual + LayerNorm (unbiased var, scalar gamma/beta).
// Optionally also emits bf16 hi/lo split of the output.
// ---------------------------------------------------------------------------
__global__ __launch_bounds__(128)
void ln_add_kernel(const float* __restrict__ X, const float* __restrict__ Z,
                   const float* __restrict__ g, const float* __restrict__ beta,
                   float* __restrict__ Out,
                   __nv_bfloat16* __restrict__ Ohi, __nv_bfloat16* __restrict__ Olo)
{
    __shared__ float red[4];
    const int row = blockIdx.x;
    const int t = threadIdx.x;
    const float4 zv = ((const float4*)(Z + (size_t)row * DD))[t];

    float s = zv.x + zv.y + zv.z + zv.w;
#pragma unroll
    for (int off = 16; off > 0; off >>= 1) s += __shfl_down_sync(0xffffffffu, s, off);
    if ((t & 31) == 0) red[t >> 5] = s;
    __syncthreads();
    float mean = (red[0] + red[1] + red[2] + red[3]) * (1.0f / DD);
    __syncthreads();

    float d0 = zv.x - mean, d1 = zv.y - mean, d2 = zv.z - mean, d3 = zv.w - mean;
    float ss = d0 * d0 + d1 * d1 + d2 * d2 + d3 * d3;
#pragma unroll
    for (int off = 16; off > 0; off >>= 1) ss += __shfl_down_sync(0xffffffffu, ss, off);
    if ((t & 31) == 0) red[t >> 5] = ss;
    __syncthreads();
    float var = (red[0] + red[1] + red[2] + red[3]) * (1.0f / (DD - 1));

    float inv = rsqrtf(var + 1e-6f);
    float gg = *g, bb = *beta;

    const float4 xv = ((const float4*)(X + (size_t)row * DD))[t];
    float4 o;
    o.x = xv.x + gg * d0 * inv + bb;
    o.y = xv.y + gg * d1 * inv + bb;
    o.z = xv.z + gg * d2 * inv + bb;
    o.w = xv.w + gg * d3 * inv + bb;
    ((float4*)(Out + (size_t)row * DD))[t] = o;

    if (Ohi) {
        size_t off = (size_t)row * DD + t * 4;
        __nv_bfloat162 h0 = __floats2bfloat162_rn(o.x, o.y);
        __nv_bfloat162 h1 = __floats2bfloat162_rn(o.z, o.w);
        __nv_bfloat162 l0 = __floats2bfloat162_rn(o.x - __bfloat162float(h0.x),
                                                  o.y - __bfloat162float(h0.y));
        __nv_bfloat162 l1 = __floats2bfloat162_rn(o.z - __bfloat162float(h1.x),
                                                  o.w - __bfloat162float(h1.y));
        *(__nv_bfloat162*)(Ohi + off)     = h0;
        *(__nv_bfloat162*)(Ohi + off + 2) = h1;
        *(__nv_bfloat162*)(Olo + off)     = l0;
        *(__nv_bfloat162*)(Olo + off + 2) = l1;
    }
}

// ---------------------------------------------------------------------------
// Launch
// ---------------------------------------------------------------------------
extern "C" void kernel_launch(void* const* d_in, const int* in_sizes, int n_in,
                              void* d_out, int out_size)
{
    const float* x    = (const float*)d_in[0];
    const void*  mraw = (const void*)d_in[1];
    const float* wq   = (const float*)d_in[2];
    const float* bq   = (const float*)d_in[3];
    const float* wk   = (const float*)d_in[4];
    const float* bk   = (const float*)d_in[5];
    const float* wv   = (const float*)d_in[6];
    const float* bv   = (const float*)d_in[7];
    const float* wo   = (const float*)d_in[8];
    const float* bo   = (const float*)d_in[9];
    const float* w1   = (const float*)d_in[10];
    const float* b1   = (const float*)d_in[11];
    const float* w2   = (const float*)d_in[12];
    const float* b2   = (const float*)d_in[13];
    const float* g1   = (const float*)d_in[14];
    const float* be1  = (const float*)d_in[15];
    const float* g2   = (const float*)d_in[16];
    const float* be2  = (const float*)d_in[17];
    float* out = (float*)d_out;

    float *pQKV, *pO, *pY, *pBias;
    __nv_bfloat16 *pAhi, *pAlo, *pFhi, *pFlo, *pWhi, *pWlo;
    unsigned char* pM; int* pMF;
    cudaGetSymbolAddress((void**)&pQKV, g_QKV);
    cudaGetSymbolAddress((void**)&pO, g_O);
    cudaGetSymbolAddress((void**)&pY, g_Y);
    cudaGetSymbolAddress((void**)&pAhi, g_Ahi);
    cudaGetSymbolAddress((void**)&pAlo, g_Alo);
    cudaGetSymbolAddress((void**)&pFhi, g_Fhi);
    cudaGetSymbolAddress((void**)&pFlo, g_Flo);
    cudaGetSymbolAddress((void**)&pWhi, g_Whi);
    cudaGetSymbolAddress((void**)&pWlo, g_Wlo);
    cudaGetSymbolAddress((void**)&pBias, g_biasQKV);
    cudaGetSymbolAddress((void**)&pM, g_mask);
    cudaGetSymbolAddress((void**)&pMF, g_mflag);

    cudaFuncSetAttribute(gemm_mma, cudaFuncAttributeMaxDynamicSharedMemorySize, GSMEM);

    // mask + bias prep
    detect_mask_kernel<<<1, 256>>>(mraw, pMF);
    expand_mask_kernel<<<(BB * SS + 255) / 256, 256>>>(mraw, pMF, pM);
    concat_bias_kernel<<<(QKVN + 255) / 256, 256>>>(bq, bk, bv, pBias);

    // weight splits (once per call; cheap)
    split_bf16_kernel<<<(DD * DD) / 1024, 256>>>(wq, pWhi + WOFF_QKV,            pWlo + WOFF_QKV,            DD * DD);
    split_bf16_kernel<<<(DD * DD) / 1024, 256>>>(wk, pWhi + WOFF_QKV + DD * DD,  pWlo + WOFF_QKV + DD * DD,  DD * DD);
    split_bf16_kernel<<<(DD * DD) / 1024, 256>>>(wv, pWhi + WOFF_QKV + 2*DD*DD,  pWlo + WOFF_QKV + 2*DD*DD,  DD * DD);
    split_bf16_kernel<<<(DD * DD) / 1024, 256>>>(wo, pWhi + WOFF_O,  pWlo + WOFF_O,  DD * DD);
    split_bf16_kernel<<<(DFF * DD) / 1024, 256>>>(w1, pWhi + WOFF_1, pWlo + WOFF_1, DFF * DD);
    split_bf16_kernel<<<(DD * DFF) / 1024, 256>>>(w2, pWhi + WOFF_2, pWlo + WOFF_2, DD * DFF);

    // x split
    split_bf16_kernel<<<(MM * DD) / 1024, 256>>>(x, pAhi, pAlo, MM * DD);

    // fused QKV projection: [M,1536]
    dim3 gQKV(QKVN / 128, MM / 128);
    gemm_mma<<<gQKV, 256, GSMEM>>>(pAhi, pAlo, pWhi + WOFF_QKV, pWlo + WOFF_QKV,
                                   pBias, pQKV, ((__nv_bfloat16*)0), ((__nv_bfloat16*)0),
                                   MM, QKVN, DD, 0);

    // attention -> bf16 split of T into pAhi/pAlo (x split no longer needed)
    dim3 gAtt(SS / 64, HH, BB);
    attention_kernel<<<gAtt, 128>>>(pQKV, pM, pAhi, pAlo);

    // WO projection -> fp32 pO
    dim3 gProj(DD / 128, MM / 128);
    gemm_mma<<<gProj, 256, GSMEM>>>(pAhi, pAlo, pWhi + WOFF_O, pWlo + WOFF_O,
                                    bo, pO, ((__nv_bfloat16*)0), ((__nv_bfloat16*)0),
                                    MM, DD, DD, 0);

    // residual 1 + LN -> Y (fp32) + Y split into pAhi/pAlo
    ln_add_kernel<<<MM, 128>>>(x, pO, g1, be1, pY, pAhi, pAlo);

    // FFN1: relu, bf16 split out only
    dim3 gFF1(DFF / 128, MM / 128);
    gemm_mma<<<gFF1, 256, GSMEM>>>(pAhi, pAlo, pWhi + WOFF_1, pWlo + WOFF_1,
                                   b1, ((float*)0), pFhi, pFlo,
                                   MM, DFF, DD, 1);

    // FFN2 -> fp32 pO
    gemm_mma<<<gProj, 256, GSMEM>>>(pFhi, pFlo, pWhi + WOFF_2, pWlo + WOFF_2,
                                    b2, pO, ((__nv_bfloat16*)0), ((__nv_bfloat16*)0),
                                    MM, DD, DFF, 0);

    // residual 2 + LN -> out
    ln_add_kernel<<<MM, 128>>>(pY, pO, g2, be2, out, ((__nv_bfloat16*)0), ((__nv_bfloat16*)0));
}

// round 7
// speedup vs baseline: 3.2474x; 2.3023x over previous
#include <cuda_runtime.h>
#include <cuda_bf16.h>
#include <math.h>
#include <stdint.h>

// Problem dims
#define BB   4
#define SS   2048
#define DD   512
#define HH   8
#define DKV  64
#define DFF  2048
#define MM   (BB * SS)     // 8192 rows
#define QKVN 1536          // fused Q|K|V output width

// ---------------------------------------------------------------------------
// Scratch (device globals — no allocation allowed)
// ---------------------------------------------------------------------------
__device__ __align__(256) float g_O[MM * DD];       // gemm fp32 out (WO / FFN2)
__device__ __align__(256) float g_Y[MM * DD];       // residual-1 output
__device__ __align__(256) __nv_bfloat16 g_QKVh[MM * QKVN];
__device__ __align__(256) __nv_bfloat16 g_QKVl[MM * QKVN];
__device__ __align__(256) __nv_bfloat16 g_Ahi[MM * DD];   // activation splits [M,512]
__device__ __align__(256) __nv_bfloat16 g_Alo[MM * DD];
__device__ __align__(256) __nv_bfloat16 g_Fhi[MM * DFF];  // FFN hidden splits
__device__ __align__(256) __nv_bfloat16 g_Flo[MM * DFF];
// weights [N,K] row-major, concatenated: qkv rows 0..1535 (K=512), wo, w1, w2
#define WOFF_QKV 0
#define WOFF_O   (QKVN * DD)
#define WOFF_1   (WOFF_O + DD * DD)
#define WOFF_2   (WOFF_1 + DFF * DD)
#define WTOT     (WOFF_2 + DD * DFF)
__device__ __align__(256) __nv_bfloat16 g_Whi[WTOT];
__device__ __align__(256) __nv_bfloat16 g_Wlo[WTOT];
__device__ float g_biasQKV[QKVN];
__device__ float g_maskSA[BB * SS * 2];   // (scale, add) per key
__device__ int g_mflag[1];

// ---------------------------------------------------------------------------
// Helpers
// ---------------------------------------------------------------------------
__device__ __forceinline__ uint32_t smem_u32(const void* p) {
    uint32_t a;
    asm("{ .reg .u64 t; cvta.to.shared.u64 t, %1; cvt.u32.u64 %0, t; }" : "=r"(a) : "l"(p));
    return a;
}
__device__ __forceinline__ void cp16(uint32_t d, const void* g) {
    asm volatile("cp.async.cg.shared.global [%0], [%1], 16;" :: "r"(d), "l"(g));
}
#define CP_COMMIT() asm volatile("cp.async.commit_group;" ::: "memory")
#define CP_WAIT0()  asm volatile("cp.async.wait_group 0;" ::: "memory")
#define CP_WAIT1()  asm volatile("cp.async.wait_group 1;" ::: "memory")

#define LDSM4(r0, r1, r2, r3, a) \
    asm volatile("ldmatrix.sync.aligned.m8n8.x4.shared.b16 {%0,%1,%2,%3}, [%4];" \
                 : "=r"(r0), "=r"(r1), "=r"(r2), "=r"(r3) : "r"(a))
#define LDSM4T(r0, r1, r2, r3, a) \
    asm volatile("ldmatrix.sync.aligned.m8n8.x4.trans.shared.b16 {%0,%1,%2,%3}, [%4];" \
                 : "=r"(r0), "=r"(r1), "=r"(r2), "=r"(r3) : "r"(a))

#define MMA16816(d, a, b) \
    asm volatile("mma.sync.aligned.m16n8k16.row.col.f32.bf16.bf16.f32 " \
                 "{%0,%1,%2,%3},{%4,%5,%6,%7},{%8,%9},{%0,%1,%2,%3};" \
                 : "+f"((d)[0]), "+f"((d)[1]), "+f"((d)[2]), "+f"((d)[3]) \
                 : "r"((a)[0]), "r"((a)[1]), "r"((a)[2]), "r"((a)[3]), \
                   "r"((b)[0]), "r"((b)[1]))

__device__ __forceinline__ uint32_t pack_bf16x2(float a, float b) {
    __nv_bfloat162 v = __floats2bfloat162_rn(a, b);
    return *(uint32_t*)&v;
}

// ---------------------------------------------------------------------------
// Mask canonicalization -> (scale, add) pairs
// ---------------------------------------------------------------------------
__global__ void detect_mask_kernel(const void* __restrict__ m, int* __restrict__ flag)
{
    __shared__ int bad_int, bad_flt;
    if (threadIdx.x == 0) { bad_int = 0; bad_flt = 0; }
    __syncthreads();
    const int* mi = (const int*)m;
    const float* mf = (const float*)m;
    for (int i = threadIdx.x; i < 2048; i += 256) {
        int vi = mi[i];
        if (vi != 0 && vi != 1) bad_int = 1;
        float vf = mf[i];
        if (vf != 0.0f && vf != 1.0f) bad_flt = 1;
    }
    __syncthreads();
    if (threadIdx.x == 0) flag[0] = bad_int ? (bad_flt ? 2 : 1) : 0;
}

__global__ void expand_mask_kernel(const void* __restrict__ m, const int* __restrict__ flag,
                                   float* __restrict__ sa)
{
    int i = blockIdx.x * 256 + threadIdx.x;
    if (i >= BB * SS) return;
    int f = flag[0];
    int v;
    if (f == 0)      v = (((const int*)m)[i]   != 0);
    else if (f == 1) v = (((const float*)m)[i] != 0.0f);
    else             v = (((const unsigned char*)m)[i] != 0);
    sa[i * 2]     = v ? 0.0f   : 0.125f;
    sa[i * 2 + 1] = v ? -1.0e9f : 0.0f;
}

__global__ void concat_bias_kernel(const float* __restrict__ a, const float* __restrict__ b,
                                   const float* __restrict__ c, float* __restrict__ o)
{
    int i = blockIdx.x * 256 + threadIdx.x;
    if (i < 512)          o[i] = a[i];
    else if (i < 1024)    o[i] = b[i - 512];
    else if (i < QKVN)    o[i] = c[i - 1024];
}

// ---------------------------------------------------------------------------
// fp32 -> bf16 hi/lo split
// ---------------------------------------------------------------------------
__global__ __launch_bounds__(256)
void split_bf16_kernel(const float* __restrict__ in, __nv_bfloat16* __restrict__ hi,
                       __nv_bfloat16* __restrict__ lo, int n)
{
    int i = (blockIdx.x * 256 + threadIdx.x) * 4;
    if (i >= n) return;
    float4 v = *(const float4*)(in + i);
    __nv_bfloat16 h0 = __float2bfloat16_rn(v.x);
    __nv_bfloat16 h1 = __float2bfloat16_rn(v.y);
    __nv_bfloat16 h2 = __float2bfloat16_rn(v.z);
    __nv_bfloat16 h3 = __float2bfloat16_rn(v.w);
    __nv_bfloat16 l0 = __float2bfloat16_rn(v.x - __bfloat162float(h0));
    __nv_bfloat16 l1 = __float2bfloat16_rn(v.y - __bfloat162float(h1));
    __nv_bfloat16 l2 = __float2bfloat16_rn(v.z - __bfloat162float(h2));
    __nv_bfloat16 l3 = __float2bfloat16_rn(v.w - __bfloat162float(h3));
    __nv_bfloat162 hv0; hv0.x = h0; hv0.y = h1;
    __nv_bfloat162 hv1; hv1.x = h2; hv1.y = h3;
    __nv_bfloat162 lv0; lv0.x = l0; lv0.y = l1;
    __nv_bfloat162 lv1; lv1.x = l2; lv1.y = l3;
    *(uint2*)(hi + i) = make_uint2(*(uint32_t*)&hv0, *(uint32_t*)&hv1);
    *(uint2*)(lo + i) = make_uint2(*(uint32_t*)&lv0, *(uint32_t*)&lv1);
}

// ---------------------------------------------------------------------------
// mma.sync bf16 split-GEMM (validated R4 @ rel_err 6e-6)
// ---------------------------------------------------------------------------
#define TPAD 40
#define TILE_B (128 * TPAD * 2)
#define STAGE_B (4 * TILE_B)
#define GSMEM (2 * STAGE_B)

__device__ __forceinline__ void gemm_issue(uint32_t sb, int stage, const __nv_bfloat16* const* srcs,
                                           int K, int kt, int tid)
{
    uint32_t stbase = sb + stage * STAGE_B;
    const int k0 = kt * 32;
#pragma unroll
    for (int t = 0; t < 4; t++) {
        const __nv_bfloat16* s = srcs[t] + k0;
#pragma unroll
        for (int i = 0; i < 2; i++) {
            int idx = tid + i * 256;
            int row = idx >> 2, ch = idx & 3;
            cp16(stbase + t * TILE_B + row * (TPAD * 2) + ch * 16,
                 s + (size_t)row * K + ch * 8);
        }
    }
    CP_COMMIT();
}

__global__ __launch_bounds__(256, 1)
void gemm_mma(const __nv_bfloat16* __restrict__ Ahi, const __nv_bfloat16* __restrict__ Alo,
              const __nv_bfloat16* __restrict__ Whi, const __nv_bfloat16* __restrict__ Wlo,
              const float* __restrict__ bias, float* __restrict__ Cf,
              __nv_bfloat16* __restrict__ Chi, __nv_bfloat16* __restrict__ Clo,
              int M, int N, int K, int relu)
{
    extern __shared__ char sm[];
    const uint32_t sb = smem_u32(sm);
    const int tid = threadIdx.x;
    const int wid = tid >> 5;
    const int lane = tid & 31;
    const int bm = blockIdx.y * 128;
    const int bn = blockIdx.x * 128;
    const int wm = (wid & 1) * 64;
    const int wn = (wid >> 1) * 32;

    const __nv_bfloat16* srcs[4];
    srcs[0] = Ahi + (size_t)bm * K;
    srcs[1] = Alo + (size_t)bm * K;
    srcs[2] = Whi + (size_t)bn * K;
    srcs[3] = Wlo + (size_t)bn * K;

    float acc[4][4][4];
#pragma unroll
    for (int i = 0; i < 4; i++)
#pragma unroll
        for (int j = 0; j < 4; j++)
#pragma unroll
            for (int r = 0; r < 4; r++) acc[i][j][r] = 0.f;

    const int KT = K >> 5;
    gemm_issue(sb, 0, srcs, K, 0, tid);
    gemm_issue(sb, 1, srcs, K, 1, tid);

    const int a_lofs = ((((lane >> 3) & 1) << 3) + (lane & 7)) * (TPAD * 2) + ((lane >> 4) << 4);
    const int b_lofs = ((((lane >> 4) & 1) << 3) + (lane & 7)) * (TPAD * 2) + (((lane >> 3) & 1) << 4);

    for (int kt = 0; kt < KT; kt++) {
        if (kt == KT - 1) { CP_WAIT0(); } else { CP_WAIT1(); }
        __syncthreads();
        const uint32_t base = sb + (kt & 1) * STAGE_B;

#pragma unroll
        for (int ks = 0; ks < 2; ks++) {
            uint32_t ah[4][4], al[4][4], bh[4][2], bl[4][2];
            const uint32_t aoff = base + (wm)*(TPAD * 2) + ks * 32 + a_lofs;
            const uint32_t boff = base + 2 * TILE_B + (wn)*(TPAD * 2) + ks * 32 + b_lofs;
#pragma unroll
            for (int i = 0; i < 4; i++) {
                LDSM4(ah[i][0], ah[i][1], ah[i][2], ah[i][3], aoff + i * 16 * (TPAD * 2));
                LDSM4(al[i][0], al[i][1], al[i][2], al[i][3], aoff + TILE_B + i * 16 * (TPAD * 2));
            }
#pragma unroll
            for (int g = 0; g < 2; g++) {
                LDSM4(bh[2 * g][0], bh[2 * g][1], bh[2 * g + 1][0], bh[2 * g + 1][1],
                      boff + g * 16 * (TPAD * 2));
                LDSM4(bl[2 * g][0], bl[2 * g][1], bl[2 * g + 1][0], bl[2 * g + 1][1],
                      boff + TILE_B + g * 16 * (TPAD * 2));
            }
#pragma unroll
            for (int i = 0; i < 4; i++)
#pragma unroll
                for (int j = 0; j < 4; j++) MMA16816(acc[i][j], ah[i], bh[j]);
#pragma unroll
            for (int i = 0; i < 4; i++)
#pragma unroll
                for (int j = 0; j < 4; j++) MMA16816(acc[i][j], al[i], bh[j]);
#pragma unroll
            for (int i = 0; i < 4; i++)
#pragma unroll
                for (int j = 0; j < 4; j++) MMA16816(acc[i][j], ah[i], bl[j]);
        }
        __syncthreads();
        if (kt + 2 < KT) gemm_issue(sb, kt & 1, srcs, K, kt + 2, tid);
    }

    const int rr = lane >> 2;
    const int cc = (lane & 3) * 2;
#pragma unroll
    for (int i = 0; i < 4; i++) {
#pragma unroll
        for (int j = 0; j < 4; j++) {
            int r0 = bm + wm + i * 16 + rr;
            int c = bn + wn + j * 8 + cc;
            float b0 = __ldg(bias + c), b1 = __ldg(bias + c + 1);
            float v00 = acc[i][j][0] + b0, v01 = acc[i][j][1] + b1;
            float v10 = acc[i][j][2] + b0, v11 = acc[i][j][3] + b1;
            if (relu) {
                v00 = fmaxf(v00, 0.f); v01 = fmaxf(v01, 0.f);
                v10 = fmaxf(v10, 0.f); v11 = fmaxf(v11, 0.f);
            }
            size_t o0 = (size_t)r0 * N + c;
            size_t o1 = (size_t)(r0 + 8) * N + c;
            if (Cf) {
                *(float2*)(Cf + o0) = make_float2(v00, v01);
                *(float2*)(Cf + o1) = make_float2(v10, v11);
            }
            if (Chi) {
                __nv_bfloat162 h0 = __floats2bfloat162_rn(v00, v01);
                __nv_bfloat162 h1 = __floats2bfloat162_rn(v10, v11);
                __nv_bfloat162 l0 = __floats2bfloat162_rn(v00 - __bfloat162float(h0.x),
                                                          v01 - __bfloat162float(h0.y));
                __nv_bfloat162 l1 = __floats2bfloat162_rn(v10 - __bfloat162float(h1.x),
                                                          v11 - __bfloat162float(h1.y));
                *(__nv_bfloat162*)(Chi + o0) = h0;
                *(__nv_bfloat162*)(Chi + o1) = h1;
                *(__nv_bfloat162*)(Clo + o0) = l0;
                *(__nv_bfloat162*)(Clo + o1) = l1;
            }
        }
    }
}

// ---------------------------------------------------------------------------
// mma.sync flash attention. Block = (b, h, 64-q-tile), 128 thr / 4 warps.
// Q/K/V come in as bf16 hi/lo [M,1536]. Output: bf16 hi/lo [M,512].
// smem layout (pitch 72 bf16 = 144B/row):
//   sQh 0, sQl 9216, sKh 18432, sKl 27648, sVh 36864, sVl 46080, maskSA 55296
// ---------------------------------------------------------------------------
#define APITCH  72
#define APITCHB 144
#define ATT_SMEM (55296 + 512)

__global__ __launch_bounds__(128, 1)
void attention_mma(const __nv_bfloat16* __restrict__ QKVh, const __nv_bfloat16* __restrict__ QKVl,
                   const float* __restrict__ maskSA,
                   __nv_bfloat16* __restrict__ Ohi, __nv_bfloat16* __restrict__ Olo)
{
    extern __shared__ char ab[];
    const uint32_t sb = smem_u32(ab);
    const int b = blockIdx.z, h = blockIdx.y, q0 = blockIdx.x * 64;
    const int tid = threadIdx.x, wid = tid >> 5, lane = tid & 31;

    const uint32_t sQh = sb, sQl = sb + 9216;
    const uint32_t sKh = sb + 18432, sKl = sb + 27648;
    const uint32_t sVh = sb + 36864, sVl = sb + 46080;
    const uint32_t sMsk = sb + 55296;

    // --- load Q hi/lo tiles (once) ---
    {
        const size_t rb = ((size_t)b * SS + q0) * QKVN + h * DKV;
#pragma unroll
        for (int i = 0; i < 8; i++) {
            int idx = tid + i * 128;             // 0..1023
            int t = idx >> 9;                    // 0 hi, 1 lo
            int row = (idx >> 3) & 63;
            int ch = idx & 7;
            const __nv_bfloat16* src = (t ? QKVl : QKVh) + rb + (size_t)row * QKVN + ch * 8;
            cp16((t ? sQl : sQh) + row * APITCHB + ch * 16, src);
        }
    }
    CP_COMMIT();

    // per-lane row state: row g = lane>>2, row g+8
    float m0 = -1e30f, m1 = -1e30f, l0 = 0.f, l1 = 0.f;
    float o[8][4];
#pragma unroll
    for (int j = 0; j < 8; j++)
#pragma unroll
        for (int r = 0; r < 4; r++) o[j][r] = 0.f;

    // ldmatrix lane offsets
    const uint32_t a_lofs = (uint32_t)((wid * 16 + (((lane >> 3) & 1) << 3) + (lane & 7)) * APITCHB
                                       + ((lane >> 4) << 4));
    const uint32_t b_lofs = (uint32_t)(((((lane >> 4) & 1) << 3) + (lane & 7)) * APITCHB
                                       + (((lane >> 3) & 1) << 4));
    const uint32_t v_lofs = (uint32_t)((lane & 15) * APITCHB + ((lane >> 4) << 4));

    for (int j0 = 0; j0 < SS; j0 += 64) {
        // --- load K/V hi/lo tiles + mask (scale,add) ---
        const size_t kb = ((size_t)b * SS + j0) * QKVN + h * DKV;
#pragma unroll
        for (int i = 0; i < 16; i++) {
            int idx = tid + i * 128;             // 0..2047
            int t = idx >> 9;                    // 0 Kh, 1 Kl, 2 Vh, 3 Vl
            int row = (idx >> 3) & 63;
            int ch = idx & 7;
            const __nv_bfloat16* base = (t == 0 || t == 2) ? QKVh : QKVl;
            size_t goff = kb + (size_t)row * QKVN + ((t >= 2) ? 1024 : 512) + ch * 8;
            uint32_t d = (t == 0 ? sKh : t == 1 ? sKl : t == 2 ? sVh : sVl) + row * APITCHB + ch * 16;
            cp16(d, base + goff);
        }
        if (tid < 32) cp16(sMsk + tid * 16, maskSA + ((size_t)b * SS + j0) * 2 + tid * 4);
        CP_COMMIT();
        CP_WAIT0();
        __syncthreads();

        // --- S = Q K^T (3-pass split) ---
        float s[8][4];
#pragma unroll
        for (int j = 0; j < 8; j++)
#pragma unroll
            for (int r = 0; r < 4; r++) s[j][r] = 0.f;

#pragma unroll
        for (int kc = 0; kc < 4; kc++) {
            uint32_t qh[4], ql[4];
            LDSM4(qh[0], qh[1], qh[2], qh[3], sQh + a_lofs + kc * 32);
            LDSM4(ql[0], ql[1], ql[2], ql[3], sQl + a_lofs + kc * 32);
#pragma unroll
            for (int g = 0; g < 4; g++) {
                uint32_t kh0[2], kh1[2], kl0[2], kl1[2];
                LDSM4(kh0[0], kh0[1], kh1[0], kh1[1], sKh + b_lofs + g * 16 * APITCHB + kc * 32);
                LDSM4(kl0[0], kl0[1], kl1[0], kl1[1], sKl + b_lofs + g * 16 * APITCHB + kc * 32);
                MMA16816(s[2 * g],     qh, kh0);
                MMA16816(s[2 * g],     ql, kh0);
                MMA16816(s[2 * g],     qh, kl0);
                MMA16816(s[2 * g + 1], qh, kh1);
                MMA16816(s[2 * g + 1], ql, kh1);
                MMA16816(s[2 * g + 1], qh, kl1);
            }
        }

        // --- scale + mask: s' = s*scale + add ---
#pragma unroll
        for (int j = 0; j < 8; j++) {
            float4 f = *(const float4*)(ab + 55296 + (j * 8 + (lane & 3) * 2) * 8);
            s[j][0] = fmaf(s[j][0], f.x, f.y);
            s[j][1] = fmaf(s[j][1], f.z, f.w);
            s[j][2] = fmaf(s[j][2], f.x, f.y);
            s[j][3] = fmaf(s[j][3], f.z, f.w);
        }

        // --- online softmax ---
        float mx0 = -1e30f, mx1 = -1e30f;
#pragma unroll
        for (int j = 0; j < 8; j++) {
            mx0 = fmaxf(mx0, fmaxf(s[j][0], s[j][1]));
            mx1 = fmaxf(mx1, fmaxf(s[j][2], s[j][3]));
        }
        mx0 = fmaxf(mx0, __shfl_xor_sync(0xffffffffu, mx0, 1));
        mx0 = fmaxf(mx0, __shfl_xor_sync(0xffffffffu, mx0, 2));
        mx1 = fmaxf(mx1, __shfl_xor_sync(0xffffffffu, mx1, 1));
        mx1 = fmaxf(mx1, __shfl_xor_sync(0xffffffffu, mx1, 2));

        float mn0 = fmaxf(m0, mx0), mn1 = fmaxf(m1, mx1);
        float al0 = __expf(m0 - mn0), al1 = __expf(m1 - mn1);
        float sum0 = 0.f, sum1 = 0.f;
#pragma unroll
        for (int j = 0; j < 8; j++) {
            s[j][0] = __expf(s[j][0] - mn0); sum0 += s[j][0];
            s[j][1] = __expf(s[j][1] - mn0); sum0 += s[j][1];
            s[j][2] = __expf(s[j][2] - mn1); sum1 += s[j][2];
            s[j][3] = __expf(s[j][3] - mn1); sum1 += s[j][3];
        }
        sum0 += __shfl_xor_sync(0xffffffffu, sum0, 1);
        sum0 += __shfl_xor_sync(0xffffffffu, sum0, 2);
        sum1 += __shfl_xor_sync(0xffffffffu, sum1, 1);
        sum1 += __shfl_xor_sync(0xffffffffu, sum1, 2);
        l0 = l0 * al0 + sum0; m0 = mn0;
        l1 = l1 * al1 + sum1; m1 = mn1;
#pragma unroll
        for (int j = 0; j < 8; j++) {
            o[j][0] *= al0; o[j][1] *= al0;
            o[j][2] *= al1; o[j][3] *= al1;
        }

        // --- O += P V (3-pass split; P from accumulators) ---
#pragma unroll
        for (int kc = 0; kc < 4; kc++) {
            uint32_t ph[4], pl[4];
            {
                int j = 2 * kc;
                float h00 = s[j][0],   h01 = s[j][1],   h10 = s[j][2],   h11 = s[j][3];
                float g00 = s[j+1][0], g01 = s[j+1][1], g10 = s[j+1][2], g11 = s[j+1][3];
                ph[0] = pack_bf16x2(h00, h01);
                ph[1] = pack_bf16x2(h10, h11);
                ph[2] = pack_bf16x2(g00, g01);
                ph[3] = pack_bf16x2(g10, g11);
                __nv_bfloat162 t0 = *(__nv_bfloat162*)&ph[0];
                __nv_bfloat162 t1 = *(__nv_bfloat162*)&ph[1];
                __nv_bfloat162 t2 = *(__nv_bfloat162*)&ph[2];
                __nv_bfloat162 t3 = *(__nv_bfloat162*)&ph[3];
                pl[0] = pack_bf16x2(h00 - __bfloat162float(t0.x), h01 - __bfloat162float(t0.y));
                pl[1] = pack_bf16x2(h10 - __bfloat162float(t1.x), h11 - __bfloat162float(t1.y));
                pl[2] = pack_bf16x2(g00 - __bfloat162float(t2.x), g01 - __bfloat162float(t2.y));
                pl[3] = pack_bf16x2(g10 - __bfloat162float(t3.x), g11 - __bfloat162float(t3.y));
            }
#pragma unroll
            for (int p = 0; p < 4; p++) {
                uint32_t vh0[2], vh1[2], vl0[2], vl1[2];
                LDSM4T(vh0[0], vh0[1], vh1[0], vh1[1],
                       sVh + v_lofs + kc * 16 * APITCHB + p * 32);
                LDSM4T(vl0[0], vl0[1], vl1[0], vl1[1],
                       sVl + v_lofs + kc * 16 * APITCHB + p * 32);
                MMA16816(o[2 * p],     ph, vh0);
                MMA16816(o[2 * p],     pl, vh0);
                MMA16816(o[2 * p],     ph, vl0);
                MMA16816(o[2 * p + 1], ph, vh1);
                MMA16816(o[2 * p + 1], pl, vh1);
                MMA16816(o[2 * p + 1], ph, vl1);
            }
        }
        __syncthreads();   // done with K/V/mask smem before next iteration's loads
    }

    // --- epilogue: write bf16 hi/lo of O ---
    // NOTE: row index includes batch offset b*SS (R6 bug: it was missing).
    const float inv0 = 1.0f / l0, inv1 = 1.0f / l1;
    const size_t rg = (size_t)b * SS + q0 + wid * 16 + (lane >> 2);
    const int cb = h * DKV + (lane & 3) * 2;
#pragma unroll
    for (int j = 0; j < 8; j++) {
        size_t off0 = rg * DD + cb + j * 8;
        size_t off1 = (rg + 8) * DD + cb + j * 8;
        float v00 = o[j][0] * inv0, v01 = o[j][1] * inv0;
        float v10 = o[j][2] * inv1, v11 = o[j][3] * inv1;
        uint32_t h0 = pack_bf16x2(v00, v01);
        uint32_t h1 = pack_bf16x2(v10, v11);
        __nv_bfloat162 t0 = *(__nv_bfloat162*)&h0;
        __nv_bfloat162 t1 = *(__nv_bfloat162*)&h1;
        uint32_t z0 = pack_bf16x2(v00 - __bfloat162float(t0.x), v01 - __bfloat162float(t0.y));
        uint32_t z1 = pack_bf16x2(v10 - __bfloat162float(t1.x), v11 - __bfloat162float(t1.y));
        *(uint32_t*)(Ohi + off0) = h0;
        *(uint32_t*)(Ohi + off1) = h1;
        *(uint32_t*)(Olo + off0) = z0;
        *(uint32_t*)(Olo + off1) = z1;
    }
}

// ---------------------------------------------------------------------------
// Residual + LayerNorm (unbiased var, scalar gamma/beta), optional bf16 split
// ---------------------------------------------------------------------------
__global__ __launch_bounds__(128)
void ln_add_kernel(const float* __restrict__ X, const float* __restrict__ Z,
                   const float* __restrict__ g, const float* __restrict__ beta,
                   float* __restrict__ Out,
                   __nv_bfloat16* __restrict__ Ohi, __nv_bfloat16* __restrict__ Olo)
{
    __shared__ float red[4];
    const int row = blockIdx.x;
    const int t = threadIdx.x;
    const float4 zv = ((const float4*)(Z + (size_t)row * DD))[t];

    float s = zv.x + zv.y + zv.z + zv.w;
#pragma unroll
    for (int off = 16; off > 0; off >>= 1) s += __shfl_down_sync(0xffffffffu, s, off);
    if ((t & 31) == 0) red[t >> 5] = s;
    __syncthreads();
    float mean = (red[0] + red[1] + red[2] + red[3]) * (1.0f / DD);
    __syncthreads();

    float d0 = zv.x - mean, d1 = zv.y - mean, d2 = zv.z - mean, d3 = zv.w - mean;
    float ss = d0 * d0 + d1 * d1 + d2 * d2 + d3 * d3;
#pragma unroll
    for (int off = 16; off > 0; off >>= 1) ss += __shfl_down_sync(0xffffffffu, ss, off);
    if ((t & 31) == 0) red[t >> 5] = ss;
    __syncthreads();
    float var = (red[0] + red[1] + red[2] + red[3]) * (1.0f / (DD - 1));

    float inv = rsqrtf(var + 1e-6f);
    float gg = *g, bb = *beta;

    const float4 xv = ((const float4*)(X + (size_t)row * DD))[t];
    float4 o;
    o.x = xv.x + gg * d0 * inv + bb;
    o.y = xv.y + gg * d1 * inv + bb;
    o.z = xv.z + gg * d2 * inv + bb;
    o.w = xv.w + gg * d3 * inv + bb;
    ((float4*)(Out + (size_t)row * DD))[t] = o;

    if (Ohi) {
        size_t off = (size_t)row * DD + t * 4;
        __nv_bfloat162 h0 = __floats2bfloat162_rn(o.x, o.y);
        __nv_bfloat162 h1 = __floats2bfloat162_rn(o.z, o.w);
        __nv_bfloat162 l0 = __floats2bfloat162_rn(o.x - __bfloat162float(h0.x),
                                                  o.y - __bfloat162float(h0.y));
        __nv_bfloat162 l1 = __floats2bfloat162_rn(o.z - __bfloat162float(h1.x),
                                                  o.w - __bfloat162float(h1.y));
        *(__nv_bfloat162*)(Ohi + off)     = h0;
        *(__nv_bfloat162*)(Ohi + off + 2) = h1;
        *(__nv_bfloat162*)(Olo + off)     = l0;
        *(__nv_bfloat162*)(Olo + off + 2) = l1;
    }
}

// ---------------------------------------------------------------------------
// Launch
// ---------------------------------------------------------------------------
extern "C" void kernel_launch(void* const* d_in, const int* in_sizes, int n_in,
                              void* d_out, int out_size)
{
    const float* x    = (const float*)d_in[0];
    const void*  mraw = (const void*)d_in[1];
    const float* wq   = (const float*)d_in[2];
    const float* bq   = (const float*)d_in[3];
    const float* wk   = (const float*)d_in[4];
    const float* bk   = (const float*)d_in[5];
    const float* wv   = (const float*)d_in[6];
    const float* bv   = (const float*)d_in[7];
    const float* wo   = (const float*)d_in[8];
    const float* bo   = (const float*)d_in[9];
    const float* w1   = (const float*)d_in[10];
    const float* b1   = (const float*)d_in[11];
    const float* w2   = (const float*)d_in[12];
    const float* b2   = (const float*)d_in[13];
    const float* g1   = (const float*)d_in[14];
    const float* be1  = (const float*)d_in[15];
    const float* g2   = (const float*)d_in[16];
    const float* be2  = (const float*)d_in[17];
    float* out = (float*)d_out;

    float *pO, *pY, *pBias, *pMSA;
    __nv_bfloat16 *pQKVh, *pQKVl, *pAhi, *pAlo, *pFhi, *pFlo, *pWhi, *pWlo;
    int* pMF;
    cudaGetSymbolAddress((void**)&pO, g_O);
    cudaGetSymbolAddress((void**)&pY, g_Y);
    cudaGetSymbolAddress((void**)&pQKVh, g_QKVh);
    cudaGetSymbolAddress((void**)&pQKVl, g_QKVl);
    cudaGetSymbolAddress((void**)&pAhi, g_Ahi);
    cudaGetSymbolAddress((void**)&pAlo, g_Alo);
    cudaGetSymbolAddress((void**)&pFhi, g_Fhi);
    cudaGetSymbolAddress((void**)&pFlo, g_Flo);
    cudaGetSymbolAddress((void**)&pWhi, g_Whi);
    cudaGetSymbolAddress((void**)&pWlo, g_Wlo);
    cudaGetSymbolAddress((void**)&pBias, g_biasQKV);
    cudaGetSymbolAddress((void**)&pMSA, g_maskSA);
    cudaGetSymbolAddress((void**)&pMF, g_mflag);

    cudaFuncSetAttribute(gemm_mma, cudaFuncAttributeMaxDynamicSharedMemorySize, GSMEM);
    cudaFuncSetAttribute(attention_mma, cudaFuncAttributeMaxDynamicSharedMemorySize, ATT_SMEM);

    // mask + bias prep
    detect_mask_kernel<<<1, 256>>>(mraw, pMF);
    expand_mask_kernel<<<(BB * SS + 255) / 256, 256>>>(mraw, pMF, pMSA);
    concat_bias_kernel<<<(QKVN + 255) / 256, 256>>>(bq, bk, bv, pBias);

    // weight splits
    split_bf16_kernel<<<(DD * DD) / 1024, 256>>>(wq, pWhi + WOFF_QKV,            pWlo + WOFF_QKV,            DD * DD);
    split_bf16_kernel<<<(DD * DD) / 1024, 256>>>(wk, pWhi + WOFF_QKV + DD * DD,  pWlo + WOFF_QKV + DD * DD,  DD * DD);
    split_bf16_kernel<<<(DD * DD) / 1024, 256>>>(wv, pWhi + WOFF_QKV + 2*DD*DD,  pWlo + WOFF_QKV + 2*DD*DD,  DD * DD);
    split_bf16_kernel<<<(DD * DD) / 1024, 256>>>(wo, pWhi + WOFF_O,  pWlo + WOFF_O,  DD * DD);
    split_bf16_kernel<<<(DFF * DD) / 1024, 256>>>(w1, pWhi + WOFF_1, pWlo + WOFF_1, DFF * DD);
    split_bf16_kernel<<<(DD * DFF) / 1024, 256>>>(w2, pWhi + WOFF_2, pWlo + WOFF_2, DD * DFF);

    // x split
    split_bf16_kernel<<<(MM * DD) / 1024, 256>>>(x, pAhi, pAlo, MM * DD);

    // fused QKV projection -> bf16 hi/lo only
    dim3 gQKV(QKVN / 128, MM / 128);
    gemm_mma<<<gQKV, 256, GSMEM>>>(pAhi, pAlo, pWhi + WOFF_QKV, pWlo + WOFF_QKV,
                                   pBias, ((float*)0), pQKVh, pQKVl,
                                   MM, QKVN, DD, 0);

    // attention (tensor-core) -> bf16 split of T into pAhi/pAlo
    dim3 gAtt(SS / 64, HH, BB);
    attention_mma<<<gAtt, 128, ATT_SMEM>>>(pQKVh, pQKVl, pMSA, pAhi, pAlo);

    // WO projection -> fp32 pO
    dim3 gProj(DD / 128, MM / 128);
    gemm_mma<<<gProj, 256, GSMEM>>>(pAhi, pAlo, pWhi + WOFF_O, pWlo + WOFF_O,
                                    bo, pO, ((__nv_bfloat16*)0), ((__nv_bfloat16*)0),
                                    MM, DD, DD, 0);

    // residual 1 + LN -> Y (fp32) + split into pAhi/pAlo
    ln_add_kernel<<<MM, 128>>>(x, pO, g1, be1, pY, pAhi, pAlo);

    // FFN1: relu, bf16 split out only
    dim3 gFF1(DFF / 128, MM / 128);
    gemm_mma<<<gFF1, 256, GSMEM>>>(pAhi, pAlo, pWhi + WOFF_1, pWlo + WOFF_1,
                                   b1, ((float*)0), pFhi, pFlo,
                                   MM, DFF, DD, 1);

    // FFN2 -> fp32 pO
    gemm_mma<<<gProj, 256, GSMEM>>>(pFhi, pFlo, pWhi + WOFF_2, pWlo + WOFF_2,
                                    b2, pO, ((__nv_bfloat16*)0), ((__nv_bfloat16*)0),
                                    MM, DD, DFF, 0);

    // residual 2 + LN -> out
    ln_add_kernel<<<MM, 128>>>(pY, pO, g2, be2, out, ((__nv_bfloat16*)0), ((__nv_bfloat16*)0));
}